// round 4
// baseline (speedup 1.0000x reference)
#include <cuda_runtime.h>
#include <cuda_bf16.h>
#include <math.h>
#include <stdint.h>

#define BATCH 4
#define SQ    2048
#define SK    2048
#define NHEAD 8
#define MROWS (BATCH*SK)   // 8192

// ---------------------------------------------------------------------------
// Device scratch
// ---------------------------------------------------------------------------
__device__ __align__(16) __nv_bfloat16 g_KP  [(long)MROWS*576];
__device__ __align__(16) __nv_bfloat16 g_Qb  [(long)MROWS*512];
__device__ __align__(16) __nv_bfloat16 g_w1t [512*576];
__device__ __align__(16) __nv_bfloat16 g_w2t [512*512];
__device__ __align__(16) __nv_bfloat16 g_wqt [512*512];
__device__ __align__(16) __nv_bfloat16 g_wkt [512*512];
__device__ __align__(16) __nv_bfloat16 g_H   [(long)MROWS*512];
__device__ __align__(16) __nv_bfloat16 g_E   [(long)MROWS*512];
__device__ __align__(16) __nv_bfloat16 g_Qp  [(long)MROWS*512];   // (B,H,Sq,64)
__device__ __align__(16) __nv_bfloat16 g_Kp  [(long)MROWS*512];   // (B,H,Sk,64)
__device__ __align__(16) __nv_bfloat16 g_expS[(long)BATCH*NHEAD*SQ*SK]; // 268MB
__device__ __align__(16) __nv_bfloat16 g_delta[(long)BATCH*SQ*SK];
__device__ __align__(16) __nv_bfloat16 g_valT[(long)BATCH*512*2048];
__device__ float g_sv[BATCH*512];
__device__ float g_headSum[(long)BATCH*NHEAD*SQ];

// ---------------------------------------------------------------------------
// MMA helpers
// ---------------------------------------------------------------------------
__device__ __forceinline__ uint32_t smem_u32(const void* p) {
    uint32_t a;
    asm("{ .reg .u64 t; cvta.to.shared.u64 t, %1; cvt.u32.u64 %0, t; }"
        : "=r"(a) : "l"(p));
    return a;
}
__device__ __forceinline__ void ldm_x4(uint32_t& r0, uint32_t& r1,
                                       uint32_t& r2, uint32_t& r3, uint32_t a) {
    asm volatile("ldmatrix.sync.aligned.m8n8.x4.shared.b16 {%0,%1,%2,%3}, [%4];"
                 : "=r"(r0), "=r"(r1), "=r"(r2), "=r"(r3) : "r"(a));
}
__device__ __forceinline__ void mma16816(float* c, uint32_t a0, uint32_t a1,
                                         uint32_t a2, uint32_t a3,
                                         uint32_t b0, uint32_t b1) {
    asm volatile("mma.sync.aligned.m16n8k16.row.col.f32.bf16.bf16.f32 "
                 "{%0,%1,%2,%3},{%4,%5,%6,%7},{%8,%9},{%0,%1,%2,%3};"
                 : "+f"(c[0]), "+f"(c[1]), "+f"(c[2]), "+f"(c[3])
                 : "r"(a0), "r"(a1), "r"(a2), "r"(a3), "r"(b0), "r"(b1));
}
#define CP_ASYNC16(dst, src) \
    asm volatile("cp.async.cg.shared.global [%0], [%1], 16;" :: "r"(dst), "l"(src))
#define CP_COMMIT() asm volatile("cp.async.commit_group;")
#define CP_WAIT(n)  asm volatile("cp.async.wait_group %0;" :: "n"(n))

// ---------------------------------------------------------------------------
// Big GEMM: C = epi(A[M,K] @ Bt[N,K]^T)
//   CTA 256x128, warp tile 64x64 (8 warps: 4m x 2n), BK=32, 3-stage cp.async,
//   ONE __syncthreads per K-iter.
// EPI: 0 relu+bias->bf16   1 tanh+bias->bf16   2 bias->bf16 head-split
//      4 +sv/2048 -> fp32
// ---------------------------------------------------------------------------
#define BIG_STAGE_BYTES 30720            // A: 256*80, B: 128*80
#define BIG_DYN (3*BIG_STAGE_BYTES)      // 92160

template<int EPI>
__global__ void __launch_bounds__(256, 1)
gemm_big(const __nv_bfloat16* __restrict__ A,
         const __nv_bfloat16* __restrict__ Bt,
         const float* __restrict__ bias,
         __nv_bfloat16* __restrict__ Cb,
         float* __restrict__ Cf,
         int K, int S, long a_bstr, long b_bstr, long c_bstr,
         const float* __restrict__ sv)
{
    extern __shared__ __align__(16) char smem[];
    __shared__ float sbias[128];

    const int tid = threadIdx.x, lane = tid & 31, wid = tid >> 5;
    const int wm = wid >> 1, wn = wid & 1;          // 4 x 2 warps
    const int g = lane >> 2, tg = lane & 3;
    const int z = blockIdx.z;
    const int m0 = blockIdx.y * 256, n0 = blockIdx.x * 128;

    A  += (long)z * a_bstr;
    Bt += (long)z * b_bstr;

    if (tid < 128) {
        if (EPI <= 2) sbias[tid] = bias[n0 + tid];
        if (EPI == 4) sbias[tid] = sv[z*512 + n0 + tid] * (1.0f/2048.0f);
    }

    float acc[4][8][4];
    #pragma unroll
    for (int i = 0; i < 4; i++)
        #pragma unroll
        for (int j = 0; j < 8; j++)
            #pragma unroll
            for (int r = 0; r < 4; r++) acc[i][j][r] = 0.f;

    const int nk = K >> 5;

    auto prefetch = [&](int t) {
        if (t >= nk) return;
        int kt = t * 32;
        char* base = smem + (t % 3) * BIG_STAGE_BYTES;
        #pragma unroll
        for (int i = 0; i < 4; i++) {                 // A: 256 rows x 4 chunks
            int ch = tid + i*256;
            int r = ch >> 2, off = (ch & 3) * 8;
            CP_ASYNC16(smem_u32(base + r*80 + off*2),
                       A + (long)(m0 + r)*K + kt + off);
        }
        #pragma unroll
        for (int i = 0; i < 2; i++) {                 // B: 128 rows x 4 chunks
            int ch = tid + i*256;
            int r = ch >> 2, off = (ch & 3) * 8;
            CP_ASYNC16(smem_u32(base + 20480 + r*80 + off*2),
                       Bt + (long)(n0 + r)*K + kt + off);
        }
    };

    prefetch(0); CP_COMMIT();
    prefetch(1); CP_COMMIT();

    const int arow = lane & 15;
    const int acol = (lane & 16) ? 8 : 0;
    const int brow = ((lane >> 4) & 1) * 8 + (lane & 7);
    const int bcol = ((lane >> 3) & 1) * 8;

    for (int t = 0; t < nk; ++t) {
        CP_WAIT(1);
        __syncthreads();
        prefetch(t + 2); CP_COMMIT();   // lands in buffer freed at t-1 (barrier-ordered)
        char* base = smem + (t % 3) * BIG_STAGE_BYTES;
        #pragma unroll
        for (int ks = 0; ks < 2; ++ks) {
            uint32_t a[4][4], b[8][2];
            #pragma unroll
            for (int mi = 0; mi < 4; ++mi) {
                uint32_t ad = smem_u32(base + (wm*64 + mi*16 + arow)*80
                                            + (ks*16 + acol)*2);
                ldm_x4(a[mi][0], a[mi][1], a[mi][2], a[mi][3], ad);
            }
            #pragma unroll
            for (int p = 0; p < 4; ++p) {
                uint32_t bd = smem_u32(base + 20480 + (wn*64 + p*16 + brow)*80
                                             + (ks*16 + bcol)*2);
                ldm_x4(b[2*p][0], b[2*p][1], b[2*p+1][0], b[2*p+1][1], bd);
            }
            #pragma unroll
            for (int mi = 0; mi < 4; ++mi)
                #pragma unroll
                for (int nj = 0; nj < 8; ++nj)
                    mma16816(acc[mi][nj], a[mi][0], a[mi][1], a[mi][2], a[mi][3],
                             b[nj][0], b[nj][1]);
        }
    }

    // ---------------- epilogue (direct register -> global) ----------------
    #pragma unroll
    for (int mi = 0; mi < 4; ++mi) {
        #pragma unroll
        for (int half = 0; half < 2; ++half) {
            int m = m0 + wm*64 + mi*16 + g + half*8;
            #pragma unroll
            for (int nj = 0; nj < 8; ++nj) {
                int nl = wn*64 + nj*8 + tg*2;
                int n = n0 + nl;
                float v0 = acc[mi][nj][half*2 + 0];
                float v1 = acc[mi][nj][half*2 + 1];
                if (EPI <= 2) {
                    v0 += sbias[nl]; v1 += sbias[nl+1];
                    if (EPI == 0) { v0 = fmaxf(v0, 0.f); v1 = fmaxf(v1, 0.f); }
                    if (EPI == 1) { v0 = tanhf(v0);      v1 = tanhf(v1); }
                    __nv_bfloat162 pk;
                    pk.x = __float2bfloat16(v0); pk.y = __float2bfloat16(v1);
                    if (EPI == 2) {
                        int b = m / S, srow = m - b*S;
                        int h = n >> 6, dd = n & 63;
                        long idx = (((long)(b*NHEAD + h)*S + srow) << 6) + dd;
                        *(__nv_bfloat162*)&Cb[idx] = pk;
                    } else {
                        *(__nv_bfloat162*)&Cb[(long)m*512 + n] = pk;
                    }
                } else { // EPI == 4
                    float o0 = v0 + sbias[nl];
                    float o1 = v1 + sbias[nl+1];
                    *(float2*)&Cf[(long)z*c_bstr + (long)m*512 + n] = make_float2(o0, o1);
                }
            }
        }
    }
}

// ---------------------------------------------------------------------------
// Score GEMM: per (b,h) 128x128 tile of exp(Qp·Kp^T / 8), K=64 single-shot.
//   8 warps 2m x 4n, warp tile 64x32. Accumulates row sums into g_headSum.
// ---------------------------------------------------------------------------
#define SC_DYN (2*128*144)   // A,B each 128 rows x 72 halves (144B)

__global__ void __launch_bounds__(256)
score_mma(float* __restrict__ rowsum)
{
    extern __shared__ __align__(16) char smem[];
    __shared__ float srs[128];

    const int tid = threadIdx.x, lane = tid & 31, wid = tid >> 5;
    const int wm = wid >> 2, wn = wid & 3;          // 2 x 4 warps
    const int g = lane >> 2, tg = lane & 3;
    const int z = blockIdx.z;
    const int m0 = blockIdx.y * 128, n0 = blockIdx.x * 128;

    const __nv_bfloat16* A  = g_Qp + (long)z * 2048 * 64;
    const __nv_bfloat16* Bt = g_Kp + (long)z * 2048 * 64;

    if (tid < 128) srs[tid] = 0.f;

    char* sA = smem;
    char* sB = smem + 128*144;
    #pragma unroll
    for (int i = 0; i < 4; i++) {          // 128 rows x 8 chunks... 1024 chunks/op
        int ch = tid + i*256;
        int r = ch >> 3, off = (ch & 7) * 8;
        CP_ASYNC16(smem_u32(sA + r*144 + off*2), A  + (long)(m0 + r)*64 + off);
        CP_ASYNC16(smem_u32(sB + r*144 + off*2), Bt + (long)(n0 + r)*64 + off);
    }
    CP_COMMIT();
    CP_WAIT(0);
    __syncthreads();

    const int arow = lane & 15;
    const int acol = (lane & 16) ? 8 : 0;
    const int brow = ((lane >> 4) & 1) * 8 + (lane & 7);
    const int bcol = ((lane >> 3) & 1) * 8;

    float acc[4][4][4];
    #pragma unroll
    for (int i = 0; i < 4; i++)
        #pragma unroll
        for (int j = 0; j < 4; j++)
            #pragma unroll
            for (int r = 0; r < 4; r++) acc[i][j][r] = 0.f;

    #pragma unroll
    for (int ks = 0; ks < 4; ++ks) {
        uint32_t a[4][4], b[4][2];
        #pragma unroll
        for (int mi = 0; mi < 4; ++mi) {
            uint32_t ad = smem_u32(sA + (wm*64 + mi*16 + arow)*144
                                      + (ks*16 + acol)*2);
            ldm_x4(a[mi][0], a[mi][1], a[mi][2], a[mi][3], ad);
        }
        #pragma unroll
        for (int p = 0; p < 2; ++p) {
            uint32_t bd = smem_u32(sB + (wn*32 + p*16 + brow)*144
                                      + (ks*16 + bcol)*2);
            ldm_x4(b[2*p][0], b[2*p][1], b[2*p+1][0], b[2*p+1][1], bd);
        }
        #pragma unroll
        for (int mi = 0; mi < 4; ++mi)
            #pragma unroll
            for (int nj = 0; nj < 4; ++nj)
                mma16816(acc[mi][nj], a[mi][0], a[mi][1], a[mi][2], a[mi][3],
                         b[nj][0], b[nj][1]);
    }

    // epilogue: exp(x/8) -> bf16 store + row sums
    #pragma unroll
    for (int mi = 0; mi < 4; ++mi) {
        #pragma unroll
        for (int half = 0; half < 2; ++half) {
            int m = m0 + wm*64 + mi*16 + g + half*8;
            float rsum = 0.f;
            #pragma unroll
            for (int nj = 0; nj < 4; ++nj) {
                int n = n0 + wn*32 + nj*8 + tg*2;
                float v0 = __expf(acc[mi][nj][half*2 + 0] * 0.125f);
                float v1 = __expf(acc[mi][nj][half*2 + 1] * 0.125f);
                __nv_bfloat162 pk;
                pk.x = __float2bfloat16(v0); pk.y = __float2bfloat16(v1);
                *(__nv_bfloat162*)&g_expS[(long)z*SQ*SK + (long)m*2048 + n] = pk;
                rsum += v0 + v1;
            }
            rsum += __shfl_xor_sync(0xffffffffu, rsum, 1);
            rsum += __shfl_xor_sync(0xffffffffu, rsum, 2);
            if (tg == 0) atomicAdd(&srs[m - m0], rsum);
        }
    }
    __syncthreads();
    if (tid < 128) atomicAdd(&rowsum[(long)z*SQ + m0 + tid], srs[tid]);
}

// ---------------------------------------------------------------------------
// Prep + combine kernels
// ---------------------------------------------------------------------------
__global__ void zero_kernel() {
    int i = blockIdx.x * blockDim.x + threadIdx.x;
    if (i < BATCH*NHEAD*SQ) g_headSum[i] = 0.f;
    if (i < BATCH*512)      g_sv[i] = 0.f;
}

__global__ void convert_concat(const float* __restrict__ key,
                               const int* __restrict__ kwpos,
                               const float* __restrict__ pe)
{
    int i = blockIdx.x * blockDim.x + threadIdx.x;
    if (i >= MROWS * 144) return;
    int row = i / 144, c4 = (i % 144) * 4;
    float4 v;
    if (c4 < 512) v = *(const float4*)&key[(long)row*512 + c4];
    else { int p = kwpos[row]; v = *(const float4*)&pe[(long)p*64 + (c4-512)]; }
    __nv_bfloat162 p0, p1;
    p0.x = __float2bfloat16(v.x); p0.y = __float2bfloat16(v.y);
    p1.x = __float2bfloat16(v.z); p1.y = __float2bfloat16(v.w);
    __nv_bfloat16* d = &g_KP[(long)row*576 + c4];
    *(__nv_bfloat162*)&d[0] = p0;
    *(__nv_bfloat162*)&d[2] = p1;
}

__global__ void conv_bf16(const float* __restrict__ src,
                          __nv_bfloat16* __restrict__ dst, int n4)
{
    int i = blockIdx.x * blockDim.x + threadIdx.x;
    if (i >= n4) return;
    float4 v = *(const float4*)&src[(long)i*4];
    __nv_bfloat162 p0, p1;
    p0.x = __float2bfloat16(v.x); p0.y = __float2bfloat16(v.y);
    p1.x = __float2bfloat16(v.z); p1.y = __float2bfloat16(v.w);
    *(__nv_bfloat162*)&dst[(long)i*4]   = p0;
    *(__nv_bfloat162*)&dst[(long)i*4+2] = p1;
}

__global__ void transpose_conv(const float* __restrict__ src,
                               __nv_bfloat16* __restrict__ dst,
                               int R, int C, long sstr, long dstr)
{
    __shared__ float t[32][33];
    src += (long)blockIdx.z * sstr;
    dst += (long)blockIdx.z * dstr;
    int r0 = blockIdx.y * 32, c0 = blockIdx.x * 32;
    int tx = threadIdx.x & 31, ty = threadIdx.x >> 5;
    #pragma unroll
    for (int i = 0; i < 4; i++)
        t[ty + i*8][tx] = src[(long)(r0 + ty + i*8)*C + c0 + tx];
    __syncthreads();
    #pragma unroll
    for (int i = 0; i < 4; i++)
        dst[(long)(c0 + ty + i*8)*R + r0 + tx] = __float2bfloat16(t[tx][ty + i*8]);
}

__global__ void colsum_kernel(const float* __restrict__ value)
{
    int b = blockIdx.z;
    int d = blockIdx.x * 128 + threadIdx.x;
    int k0 = blockIdx.y * 128;
    float s = 0.f;
    const float* base = value + ((long)b*SK + k0)*512 + d;
    #pragma unroll 8
    for (int k = 0; k < 128; k++) s += base[(long)k*512];
    atomicAdd(&g_sv[b*512 + d], s);
}

__global__ void combine_kernel(const int* __restrict__ kwpos,
                               float* __restrict__ adj)
{
    int bq = blockIdx.x;
    int b  = bq >> 11;
    int q  = bq & 2047;
    int tid = threadIdx.x;

    __shared__ float invHS[NHEAD];
    if (tid < NHEAD)
        invHS[tid] = 1.0f / g_headSum[(long)(b*NHEAD + tid)*SQ + q];
    __syncthreads();

    float e[8];
    float sum = 0.f;
    #pragma unroll
    for (int i = 0; i < 8; i++) {
        int k = tid + i*256;
        float a = 0.f;
        #pragma unroll
        for (int h = 0; h < NHEAD; h++)
            a = fmaf(__bfloat162float(
                    g_expS[((long)(b*NHEAD + h)*SQ + q)*SK + k]), invHS[h], a);
        a *= 0.125f;
        int kp = kwpos[b*SK + k];
        float dw = 1.0f / (1.0f + fabsf((float)(q - kp)));
        e[i] = __expf(a * dw);
        sum += e[i];
    }
    #pragma unroll
    for (int s = 16; s > 0; s >>= 1) sum += __shfl_xor_sync(0xffffffffu, sum, s);
    __shared__ float wred[8];
    if ((tid & 31) == 0) wred[tid >> 5] = sum;
    __syncthreads();
    float tot = wred[0];
    #pragma unroll
    for (int w = 1; w < 8; w++) tot += wred[w];
    float inv = 1.0f / tot;

    long base = (long)bq * SK;
    #pragma unroll
    for (int i = 0; i < 8; i++) {
        int k = tid + i*256;
        float av = e[i] * inv;
        adj[base + k] = av;
        g_delta[base + k] = __float2bfloat16(av - (1.f/2048.f));
    }
}

// ---------------------------------------------------------------------------
extern "C" void kernel_launch(void* const* d_in, const int* in_sizes, int n_in,
                              void* d_out, int out_size)
{
    const float* query   = (const float*)d_in[0];
    const float* key     = (const float*)d_in[1];
    const float* value   = (const float*)d_in[2];
    const int*   kwpos   = (const int*)  d_in[3];
    const float* pos_emb = (const float*)d_in[4];
    const float* w1      = (const float*)d_in[5];
    const float* b1      = (const float*)d_in[6];
    const float* w2      = (const float*)d_in[7];
    const float* b2      = (const float*)d_in[8];
    const float* wq      = (const float*)d_in[9];
    const float* bq      = (const float*)d_in[10];
    const float* wk      = (const float*)d_in[11];
    const float* bk      = (const float*)d_in[12];

    float* out = (float*)d_out;
    float* adj = out + (long)BATCH*SQ*512;

    void *gKP, *gQb, *gw1t, *gw2t, *gwqt, *gwkt, *gH, *gE, *gQp, *gKp,
         *gdelta, *gvalT, *gsv, *ghs;
    cudaGetSymbolAddress(&gKP,   g_KP);
    cudaGetSymbolAddress(&gQb,   g_Qb);
    cudaGetSymbolAddress(&gw1t,  g_w1t);
    cudaGetSymbolAddress(&gw2t,  g_w2t);
    cudaGetSymbolAddress(&gwqt,  g_wqt);
    cudaGetSymbolAddress(&gwkt,  g_wkt);
    cudaGetSymbolAddress(&gH,    g_H);
    cudaGetSymbolAddress(&gE,    g_E);
    cudaGetSymbolAddress(&gQp,   g_Qp);
    cudaGetSymbolAddress(&gKp,   g_Kp);
    cudaGetSymbolAddress(&gdelta,g_delta);
    cudaGetSymbolAddress(&gvalT, g_valT);
    cudaGetSymbolAddress(&gsv,   g_sv);
    cudaGetSymbolAddress(&ghs,   g_headSum);

    cudaFuncSetAttribute(gemm_big<0>, cudaFuncAttributeMaxDynamicSharedMemorySize, BIG_DYN);
    cudaFuncSetAttribute(gemm_big<1>, cudaFuncAttributeMaxDynamicSharedMemorySize, BIG_DYN);
    cudaFuncSetAttribute(gemm_big<2>, cudaFuncAttributeMaxDynamicSharedMemorySize, BIG_DYN);
    cudaFuncSetAttribute(gemm_big<4>, cudaFuncAttributeMaxDynamicSharedMemorySize, BIG_DYN);
    cudaFuncSetAttribute(score_mma,   cudaFuncAttributeMaxDynamicSharedMemorySize, SC_DYN);

    // launch order: index 5 = gemm_big<1> (E) for ncu -s 5
    zero_kernel<<<(BATCH*NHEAD*SQ + 255)/256, 256>>>();                        // 0
    convert_concat<<<(MROWS*144 + 255)/256, 256>>>(key, kwpos, pos_emb);       // 1
    transpose_conv<<<dim3(16, 18, 1), 256>>>(w1, (__nv_bfloat16*)gw1t, 576, 512, 0, 0); // 2
    gemm_big<0><<<dim3(4, 32, 1), 256, BIG_DYN>>>(                             // 3: H
        (__nv_bfloat16*)gKP, (__nv_bfloat16*)gw1t, b1,
        (__nv_bfloat16*)gH, nullptr, 576, SK, 0, 0, 0, nullptr);
    transpose_conv<<<dim3(16, 16, 1), 256>>>(w2, (__nv_bfloat16*)gw2t, 512, 512, 0, 0); // 4
    gemm_big<1><<<dim3(4, 32, 1), 256, BIG_DYN>>>(                             // 5: E
        (__nv_bfloat16*)gH, (__nv_bfloat16*)gw2t, b2,
        (__nv_bfloat16*)gE, nullptr, 512, SK, 0, 0, 0, nullptr);
    transpose_conv<<<dim3(16, 16, 1), 256>>>(wk, (__nv_bfloat16*)gwkt, 512, 512, 0, 0); // 6
    gemm_big<2><<<dim3(4, 32, 1), 256, BIG_DYN>>>(                             // 7: Kp
        (__nv_bfloat16*)gE, (__nv_bfloat16*)gwkt, bk,
        (__nv_bfloat16*)gKp, nullptr, 512, SK, 0, 0, 0, nullptr);
    conv_bf16<<<(MROWS*512/4 + 255)/256, 256>>>(query, (__nv_bfloat16*)gQb, MROWS*512/4); // 8
    transpose_conv<<<dim3(16, 16, 1), 256>>>(wq, (__nv_bfloat16*)gwqt, 512, 512, 0, 0);   // 9
    gemm_big<2><<<dim3(4, 32, 1), 256, BIG_DYN>>>(                             // 10: Qp
        (__nv_bfloat16*)gQb, (__nv_bfloat16*)gwqt, bq,
        (__nv_bfloat16*)gQp, nullptr, 512, SQ, 0, 0, 0, nullptr);
    score_mma<<<dim3(16, 16, BATCH*NHEAD), 256, SC_DYN>>>((float*)ghs);        // 11
    combine_kernel<<<BATCH*SQ, 256>>>(kwpos, adj);                             // 12
    transpose_conv<<<dim3(16, 64, BATCH), 256>>>(value, (__nv_bfloat16*)gvalT, // 13
                                                 SK, 512, (long)SK*512, (long)512*SK);
    colsum_kernel<<<dim3(4, 16, BATCH), 128>>>(value);                         // 14
    gemm_big<4><<<dim3(4, 8, BATCH), 256, BIG_DYN>>>(                          // 15: out
        (__nv_bfloat16*)gdelta, (__nv_bfloat16*)gvalT, nullptr,
        nullptr, out, 2048, SQ, (long)SQ*SK, (long)512*2048, (long)SQ*512,
        (const float*)gsv);
}

// round 5
// speedup vs baseline: 1.0421x; 1.0421x over previous
#include <cuda_runtime.h>
#include <cuda_bf16.h>
#include <math.h>
#include <stdint.h>

#define BATCH 4
#define SQ    2048
#define SK    2048
#define NHEAD 8
#define MROWS (BATCH*SK)   // 8192

// ---------------------------------------------------------------------------
// Device scratch
// ---------------------------------------------------------------------------
__device__ __align__(16) __nv_bfloat16 g_KP  [(long)MROWS*576];
__device__ __align__(16) __nv_bfloat16 g_Qb  [(long)MROWS*512];
__device__ __align__(16) __nv_bfloat16 g_w1t [512*576];
__device__ __align__(16) __nv_bfloat16 g_w2t [512*512];
__device__ __align__(16) __nv_bfloat16 g_wqt [512*512];
__device__ __align__(16) __nv_bfloat16 g_wkt [512*512];
__device__ __align__(16) __nv_bfloat16 g_H   [(long)MROWS*512];
__device__ __align__(16) __nv_bfloat16 g_E   [(long)MROWS*512];
__device__ __align__(16) __nv_bfloat16 g_Qp  [(long)MROWS*512];   // (B,H,Sq,64)
__device__ __align__(16) __nv_bfloat16 g_Kp  [(long)MROWS*512];   // (B,H,Sk,64)
__device__ __align__(16) __nv_bfloat16 g_expS[(long)BATCH*NHEAD*SQ*SK]; // 268MB
__device__ __align__(16) __nv_bfloat16 g_delta[(long)BATCH*SQ*SK];
__device__ __align__(16) __nv_bfloat16 g_valT[(long)BATCH*512*2048];
__device__ float g_sv[BATCH*512];
__device__ float g_headSum[(long)BATCH*NHEAD*SQ];

// ---------------------------------------------------------------------------
// MMA helpers
// ---------------------------------------------------------------------------
__device__ __forceinline__ uint32_t smem_u32(const void* p) {
    uint32_t a;
    asm("{ .reg .u64 t; cvta.to.shared.u64 t, %1; cvt.u32.u64 %0, t; }"
        : "=r"(a) : "l"(p));
    return a;
}
__device__ __forceinline__ void ldm_x4(uint32_t& r0, uint32_t& r1,
                                       uint32_t& r2, uint32_t& r3, uint32_t a) {
    asm volatile("ldmatrix.sync.aligned.m8n8.x4.shared.b16 {%0,%1,%2,%3}, [%4];"
                 : "=r"(r0), "=r"(r1), "=r"(r2), "=r"(r3) : "r"(a));
}
__device__ __forceinline__ void mma16816(float* c, uint32_t a0, uint32_t a1,
                                         uint32_t a2, uint32_t a3,
                                         uint32_t b0, uint32_t b1) {
    asm volatile("mma.sync.aligned.m16n8k16.row.col.f32.bf16.bf16.f32 "
                 "{%0,%1,%2,%3},{%4,%5,%6,%7},{%8,%9},{%0,%1,%2,%3};"
                 : "+f"(c[0]), "+f"(c[1]), "+f"(c[2]), "+f"(c[3])
                 : "r"(a0), "r"(a1), "r"(a2), "r"(a3), "r"(b0), "r"(b1));
}
#define CP_ASYNC16(dst, src) \
    asm volatile("cp.async.cg.shared.global [%0], [%1], 16;" :: "r"(dst), "l"(src))
#define CP_COMMIT() asm volatile("cp.async.commit_group;")
#define CP_WAIT(n)  asm volatile("cp.async.wait_group %0;" :: "n"(n))

// ---------------------------------------------------------------------------
// GEMM 128x128: C = epi(A[M,K] @ Bt[N,K]^T)
//   256 threads, 8 warps (2m x 4n), warp tile 64x32, BK=32, 3-stage cp.async,
//   one __syncthreads per K-iter, 2 CTAs/SM.
// EPI: 0 relu+bias->bf16   1 tanh+bias->bf16   2 bias->bf16 head-split
//      4 +sv/2048 -> fp32
// ---------------------------------------------------------------------------
#define STAGE_BYTES 20480            // A: 128*80, B: 128*80
#define GEMM_DYN (3*STAGE_BYTES)     // 61440

template<int EPI>
__global__ void __launch_bounds__(256, 2)
gemm128(const __nv_bfloat16* __restrict__ A,
        const __nv_bfloat16* __restrict__ Bt,
        const float* __restrict__ bias,
        __nv_bfloat16* __restrict__ Cb,
        float* __restrict__ Cf,
        int K, int S, long a_bstr, long b_bstr, long c_bstr,
        const float* __restrict__ sv)
{
    extern __shared__ __align__(16) char smem[];
    __shared__ float sbias[128];

    const int tid = threadIdx.x, lane = tid & 31, wid = tid >> 5;
    const int wm = wid >> 2, wn = wid & 3;          // 2 x 4 warps
    const int g = lane >> 2, tg = lane & 3;
    const int z = blockIdx.z;
    const int m0 = blockIdx.y * 128, n0 = blockIdx.x * 128;

    A  += (long)z * a_bstr;
    Bt += (long)z * b_bstr;

    if (tid < 128) {
        if (EPI <= 2) sbias[tid] = bias[n0 + tid];
        if (EPI == 4) sbias[tid] = sv[z*512 + n0 + tid] * (1.0f/2048.0f);
    }

    float acc[4][4][4];
    #pragma unroll
    for (int i = 0; i < 4; i++)
        #pragma unroll
        for (int j = 0; j < 4; j++)
            #pragma unroll
            for (int r = 0; r < 4; r++) acc[i][j][r] = 0.f;

    const int nk = K >> 5;

    auto prefetch = [&](int t) {
        if (t >= nk) return;
        int kt = t * 32;
        char* base = smem + (t % 3) * STAGE_BYTES;
        #pragma unroll
        for (int i = 0; i < 2; i++) {                 // A: 128 rows x 4 chunks
            int ch = tid + i*256;
            int r = ch >> 2, off = (ch & 3) * 8;
            CP_ASYNC16(smem_u32(base + r*80 + off*2),
                       A + (long)(m0 + r)*K + kt + off);
        }
        #pragma unroll
        for (int i = 0; i < 2; i++) {                 // B: 128 rows x 4 chunks
            int ch = tid + i*256;
            int r = ch >> 2, off = (ch & 3) * 8;
            CP_ASYNC16(smem_u32(base + 10240 + r*80 + off*2),
                       Bt + (long)(n0 + r)*K + kt + off);
        }
    };

    prefetch(0); CP_COMMIT();
    prefetch(1); CP_COMMIT();

    const int arow = lane & 15;
    const int acol = (lane & 16) ? 8 : 0;
    const int brow = ((lane >> 4) & 1) * 8 + (lane & 7);
    const int bcol = ((lane >> 3) & 1) * 8;

    for (int t = 0; t < nk; ++t) {
        CP_WAIT(1);
        __syncthreads();
        prefetch(t + 2); CP_COMMIT();   // buffer freed at t-1, barrier-ordered
        char* base = smem + (t % 3) * STAGE_BYTES;
        #pragma unroll
        for (int ks = 0; ks < 2; ++ks) {
            uint32_t a[4][4], b[4][2];
            #pragma unroll
            for (int mi = 0; mi < 4; ++mi) {
                uint32_t ad = smem_u32(base + (wm*64 + mi*16 + arow)*80
                                            + (ks*16 + acol)*2);
                ldm_x4(a[mi][0], a[mi][1], a[mi][2], a[mi][3], ad);
            }
            #pragma unroll
            for (int p = 0; p < 2; ++p) {
                uint32_t bd = smem_u32(base + 10240 + (wn*32 + p*16 + brow)*80
                                             + (ks*16 + bcol)*2);
                ldm_x4(b[2*p][0], b[2*p][1], b[2*p+1][0], b[2*p+1][1], bd);
            }
            #pragma unroll
            for (int mi = 0; mi < 4; ++mi)
                #pragma unroll
                for (int nj = 0; nj < 4; ++nj)
                    mma16816(acc[mi][nj], a[mi][0], a[mi][1], a[mi][2], a[mi][3],
                             b[nj][0], b[nj][1]);
        }
    }

    // ---------------- epilogue (register -> global) ----------------
    #pragma unroll
    for (int mi = 0; mi < 4; ++mi) {
        #pragma unroll
        for (int half = 0; half < 2; ++half) {
            int m = m0 + wm*64 + mi*16 + g + half*8;
            #pragma unroll
            for (int nj = 0; nj < 4; ++nj) {
                int nl = wn*32 + nj*8 + tg*2;
                int n = n0 + nl;
                float v0 = acc[mi][nj][half*2 + 0];
                float v1 = acc[mi][nj][half*2 + 1];
                if (EPI <= 2) {
                    v0 += sbias[nl]; v1 += sbias[nl+1];
                    if (EPI == 0) { v0 = fmaxf(v0, 0.f); v1 = fmaxf(v1, 0.f); }
                    if (EPI == 1) { v0 = tanhf(v0);      v1 = tanhf(v1); }
                    __nv_bfloat162 pk;
                    pk.x = __float2bfloat16(v0); pk.y = __float2bfloat16(v1);
                    if (EPI == 2) {
                        int b = m / S, srow = m - b*S;
                        int h = n >> 6, dd = n & 63;
                        long idx = (((long)(b*NHEAD + h)*S + srow) << 6) + dd;
                        *(__nv_bfloat162*)&Cb[idx] = pk;
                    } else {
                        *(__nv_bfloat162*)&Cb[(long)m*512 + n] = pk;
                    }
                } else { // EPI == 4
                    float o0 = v0 + sbias[nl];
                    float o1 = v1 + sbias[nl+1];
                    *(float2*)&Cf[(long)z*c_bstr + (long)m*512 + n] = make_float2(o0, o1);
                }
            }
        }
    }
}

// ---------------------------------------------------------------------------
// Score GEMM: per (b,h) 128x128 tile of exp(Qp·Kp^T / 8), K=64 single-shot.
// ---------------------------------------------------------------------------
#define SC_DYN (2*128*144)

__global__ void __launch_bounds__(256)
score_mma(float* __restrict__ rowsum)
{
    extern __shared__ __align__(16) char smem[];
    __shared__ float srs[128];

    const int tid = threadIdx.x, lane = tid & 31, wid = tid >> 5;
    const int wm = wid >> 2, wn = wid & 3;
    const int g = lane >> 2, tg = lane & 3;
    const int z = blockIdx.z;
    const int m0 = blockIdx.y * 128, n0 = blockIdx.x * 128;

    const __nv_bfloat16* A  = g_Qp + (long)z * 2048 * 64;
    const __nv_bfloat16* Bt = g_Kp + (long)z * 2048 * 64;

    if (tid < 128) srs[tid] = 0.f;

    char* sA = smem;
    char* sB = smem + 128*144;
    #pragma unroll
    for (int i = 0; i < 4; i++) {
        int ch = tid + i*256;
        int r = ch >> 3, off = (ch & 7) * 8;
        CP_ASYNC16(smem_u32(sA + r*144 + off*2), A  + (long)(m0 + r)*64 + off);
        CP_ASYNC16(smem_u32(sB + r*144 + off*2), Bt + (long)(n0 + r)*64 + off);
    }
    CP_COMMIT();
    CP_WAIT(0);
    __syncthreads();

    const int arow = lane & 15;
    const int acol = (lane & 16) ? 8 : 0;
    const int brow = ((lane >> 4) & 1) * 8 + (lane & 7);
    const int bcol = ((lane >> 3) & 1) * 8;

    float acc[4][4][4];
    #pragma unroll
    for (int i = 0; i < 4; i++)
        #pragma unroll
        for (int j = 0; j < 4; j++)
            #pragma unroll
            for (int r = 0; r < 4; r++) acc[i][j][r] = 0.f;

    #pragma unroll
    for (int ks = 0; ks < 4; ++ks) {
        uint32_t a[4][4], b[4][2];
        #pragma unroll
        for (int mi = 0; mi < 4; ++mi) {
            uint32_t ad = smem_u32(sA + (wm*64 + mi*16 + arow)*144
                                      + (ks*16 + acol)*2);
            ldm_x4(a[mi][0], a[mi][1], a[mi][2], a[mi][3], ad);
        }
        #pragma unroll
        for (int p = 0; p < 2; ++p) {
            uint32_t bd = smem_u32(sB + (wn*32 + p*16 + brow)*144
                                      + (ks*16 + bcol)*2);
            ldm_x4(b[2*p][0], b[2*p][1], b[2*p+1][0], b[2*p+1][1], bd);
        }
        #pragma unroll
        for (int mi = 0; mi < 4; ++mi)
            #pragma unroll
            for (int nj = 0; nj < 4; ++nj)
                mma16816(acc[mi][nj], a[mi][0], a[mi][1], a[mi][2], a[mi][3],
                         b[nj][0], b[nj][1]);
    }

    #pragma unroll
    for (int mi = 0; mi < 4; ++mi) {
        #pragma unroll
        for (int half = 0; half < 2; ++half) {
            int m = m0 + wm*64 + mi*16 + g + half*8;
            float rsum = 0.f;
            #pragma unroll
            for (int nj = 0; nj < 4; ++nj) {
                int n = n0 + wn*32 + nj*8 + tg*2;
                float v0 = __expf(acc[mi][nj][half*2 + 0] * 0.125f);
                float v1 = __expf(acc[mi][nj][half*2 + 1] * 0.125f);
                __nv_bfloat162 pk;
                pk.x = __float2bfloat16(v0); pk.y = __float2bfloat16(v1);
                *(__nv_bfloat162*)&g_expS[(long)z*SQ*SK + (long)m*2048 + n] = pk;
                rsum += v0 + v1;
            }
            rsum += __shfl_xor_sync(0xffffffffu, rsum, 1);
            rsum += __shfl_xor_sync(0xffffffffu, rsum, 2);
            if (tg == 0) atomicAdd(&srs[m - m0], rsum);
        }
    }
    __syncthreads();
    if (tid < 128) atomicAdd(&rowsum[(long)z*SQ + m0 + tid], srs[tid]);
}

// ---------------------------------------------------------------------------
// Prep + combine kernels
// ---------------------------------------------------------------------------
__global__ void zero_kernel() {
    int i = blockIdx.x * blockDim.x + threadIdx.x;
    if (i < BATCH*NHEAD*SQ) g_headSum[i] = 0.f;
    if (i < BATCH*512)      g_sv[i] = 0.f;
}

__global__ void convert_concat(const float* __restrict__ key,
                               const int* __restrict__ kwpos,
                               const float* __restrict__ pe)
{
    int i = blockIdx.x * blockDim.x + threadIdx.x;
    if (i >= MROWS * 144) return;
    int row = i / 144, c4 = (i % 144) * 4;
    float4 v;
    if (c4 < 512) v = *(const float4*)&key[(long)row*512 + c4];
    else { int p = kwpos[row]; v = *(const float4*)&pe[(long)p*64 + (c4-512)]; }
    __nv_bfloat162 p0, p1;
    p0.x = __float2bfloat16(v.x); p0.y = __float2bfloat16(v.y);
    p1.x = __float2bfloat16(v.z); p1.y = __float2bfloat16(v.w);
    __nv_bfloat16* d = &g_KP[(long)row*576 + c4];
    *(__nv_bfloat162*)&d[0] = p0;
    *(__nv_bfloat162*)&d[2] = p1;
}

__global__ void conv_bf16(const float* __restrict__ src,
                          __nv_bfloat16* __restrict__ dst, int n4)
{
    int i = blockIdx.x * blockDim.x + threadIdx.x;
    if (i >= n4) return;
    float4 v = *(const float4*)&src[(long)i*4];
    __nv_bfloat162 p0, p1;
    p0.x = __float2bfloat16(v.x); p0.y = __float2bfloat16(v.y);
    p1.x = __float2bfloat16(v.z); p1.y = __float2bfloat16(v.w);
    *(__nv_bfloat162*)&dst[(long)i*4]   = p0;
    *(__nv_bfloat162*)&dst[(long)i*4+2] = p1;
}

__global__ void transpose_conv(const float* __restrict__ src,
                               __nv_bfloat16* __restrict__ dst,
                               int R, int C)
{
    __shared__ float t[32][33];
    int r0 = blockIdx.y * 32, c0 = blockIdx.x * 32;
    int tx = threadIdx.x & 31, ty = threadIdx.x >> 5;
    #pragma unroll
    for (int i = 0; i < 4; i++)
        t[ty + i*8][tx] = src[(long)(r0 + ty + i*8)*C + c0 + tx];
    __syncthreads();
    #pragma unroll
    for (int i = 0; i < 4; i++)
        dst[(long)(c0 + ty + i*8)*R + r0 + tx] = __float2bfloat16(t[tx][ty + i*8]);
}

// value transpose + fused column sums
__global__ void transpose_val(const float* __restrict__ value)
{
    __shared__ float t[32][33];
    int b = blockIdx.z;
    const float* src = value + (long)b*SK*512;
    __nv_bfloat16* dst = g_valT + (long)b*512*2048;
    int r0 = blockIdx.y * 32, c0 = blockIdx.x * 32;   // r=k, c=d
    int tx = threadIdx.x & 31, ty = threadIdx.x >> 5;
    #pragma unroll
    for (int i = 0; i < 4; i++)
        t[ty + i*8][tx] = src[(long)(r0 + ty + i*8)*512 + c0 + tx];
    __syncthreads();
    #pragma unroll
    for (int i = 0; i < 4; i++)
        dst[(long)(c0 + ty + i*8)*2048 + r0 + tx] = __float2bfloat16(t[tx][ty + i*8]);
    if (threadIdx.x < 32) {
        float s = 0.f;
        #pragma unroll
        for (int rl = 0; rl < 32; rl++) s += t[rl][threadIdx.x];
        atomicAdd(&g_sv[b*512 + c0 + threadIdx.x], s);
    }
}

__global__ void combine_kernel(const int* __restrict__ kwpos,
                               float* __restrict__ adj)
{
    int bq = blockIdx.x;
    int b  = bq >> 11;
    int q  = bq & 2047;
    int tid = threadIdx.x;

    __shared__ float invHS[NHEAD];
    if (tid < NHEAD)
        invHS[tid] = 1.0f / g_headSum[(long)(b*NHEAD + tid)*SQ + q];
    __syncthreads();

    float e[8];
    float sum = 0.f;
    #pragma unroll
    for (int i = 0; i < 8; i++) {
        int k = tid + i*256;
        float a = 0.f;
        #pragma unroll
        for (int h = 0; h < NHEAD; h++)
            a = fmaf(__bfloat162float(
                    g_expS[((long)(b*NHEAD + h)*SQ + q)*SK + k]), invHS[h], a);
        a *= 0.125f;
        int kp = kwpos[b*SK + k];
        float dw = 1.0f / (1.0f + fabsf((float)(q - kp)));
        e[i] = __expf(a * dw);
        sum += e[i];
    }
    #pragma unroll
    for (int s = 16; s > 0; s >>= 1) sum += __shfl_xor_sync(0xffffffffu, sum, s);
    __shared__ float wred[8];
    if ((tid & 31) == 0) wred[tid >> 5] = sum;
    __syncthreads();
    float tot = wred[0];
    #pragma unroll
    for (int w = 1; w < 8; w++) tot += wred[w];
    float inv = 1.0f / tot;

    long base = (long)bq * SK;
    #pragma unroll
    for (int i = 0; i < 8; i++) {
        int k = tid + i*256;
        float av = e[i] * inv;
        adj[base + k] = av;
        g_delta[base + k] = __float2bfloat16(av - (1.f/2048.f));
    }
}

// ---------------------------------------------------------------------------
extern "C" void kernel_launch(void* const* d_in, const int* in_sizes, int n_in,
                              void* d_out, int out_size)
{
    const float* query   = (const float*)d_in[0];
    const float* key     = (const float*)d_in[1];
    const float* value   = (const float*)d_in[2];
    const int*   kwpos   = (const int*)  d_in[3];
    const float* pos_emb = (const float*)d_in[4];
    const float* w1      = (const float*)d_in[5];
    const float* b1      = (const float*)d_in[6];
    const float* w2      = (const float*)d_in[7];
    const float* b2      = (const float*)d_in[8];
    const float* wq      = (const float*)d_in[9];
    const float* bq      = (const float*)d_in[10];
    const float* wk      = (const float*)d_in[11];
    const float* bk      = (const float*)d_in[12];

    float* out = (float*)d_out;
    float* adj = out + (long)BATCH*SQ*512;

    void *gKP, *gQb, *gw1t, *gw2t, *gwqt, *gwkt, *gH, *gE, *gQp, *gKp,
         *gdelta, *gvalT, *gsv, *ghs;
    cudaGetSymbolAddress(&gKP,   g_KP);
    cudaGetSymbolAddress(&gQb,   g_Qb);
    cudaGetSymbolAddress(&gw1t,  g_w1t);
    cudaGetSymbolAddress(&gw2t,  g_w2t);
    cudaGetSymbolAddress(&gwqt,  g_wqt);
    cudaGetSymbolAddress(&gwkt,  g_wkt);
    cudaGetSymbolAddress(&gH,    g_H);
    cudaGetSymbolAddress(&gE,    g_E);
    cudaGetSymbolAddress(&gQp,   g_Qp);
    cudaGetSymbolAddress(&gKp,   g_Kp);
    cudaGetSymbolAddress(&gdelta,g_delta);
    cudaGetSymbolAddress(&gvalT, g_valT);
    cudaGetSymbolAddress(&gsv,   g_sv);
    cudaGetSymbolAddress(&ghs,   g_headSum);

    cudaFuncSetAttribute(gemm128<0>, cudaFuncAttributeMaxDynamicSharedMemorySize, GEMM_DYN);
    cudaFuncSetAttribute(gemm128<1>, cudaFuncAttributeMaxDynamicSharedMemorySize, GEMM_DYN);
    cudaFuncSetAttribute(gemm128<2>, cudaFuncAttributeMaxDynamicSharedMemorySize, GEMM_DYN);
    cudaFuncSetAttribute(gemm128<4>, cudaFuncAttributeMaxDynamicSharedMemorySize, GEMM_DYN);
    cudaFuncSetAttribute(score_mma,  cudaFuncAttributeMaxDynamicSharedMemorySize, SC_DYN);

    // launch order: index 5 = gemm128<1> (E) for ncu -s 5
    zero_kernel<<<(BATCH*NHEAD*SQ + 255)/256, 256>>>();                        // 0
    convert_concat<<<(MROWS*144 + 255)/256, 256>>>(key, kwpos, pos_emb);       // 1
    transpose_conv<<<dim3(16, 18, 1), 256>>>(w1, (__nv_bfloat16*)gw1t, 576, 512); // 2
    gemm128<0><<<dim3(4, 64, 1), 256, GEMM_DYN>>>(                             // 3: H
        (__nv_bfloat16*)gKP, (__nv_bfloat16*)gw1t, b1,
        (__nv_bfloat16*)gH, nullptr, 576, SK, 0, 0, 0, nullptr);
    transpose_conv<<<dim3(16, 16, 1), 256>>>(w2, (__nv_bfloat16*)gw2t, 512, 512); // 4
    gemm128<1><<<dim3(4, 64, 1), 256, GEMM_DYN>>>(                             // 5: E
        (__nv_bfloat16*)gH, (__nv_bfloat16*)gw2t, b2,
        (__nv_bfloat16*)gE, nullptr, 512, SK, 0, 0, 0, nullptr);
    transpose_conv<<<dim3(16, 16, 1), 256>>>(wk, (__nv_bfloat16*)gwkt, 512, 512); // 6
    gemm128<2><<<dim3(4, 64, 1), 256, GEMM_DYN>>>(                             // 7: Kp
        (__nv_bfloat16*)gE, (__nv_bfloat16*)gwkt, bk,
        (__nv_bfloat16*)gKp, nullptr, 512, SK, 0, 0, 0, nullptr);
    conv_bf16<<<(MROWS*512/4 + 255)/256, 256>>>(query, (__nv_bfloat16*)gQb, MROWS*512/4); // 8
    transpose_conv<<<dim3(16, 16, 1), 256>>>(wq, (__nv_bfloat16*)gwqt, 512, 512);         // 9
    gemm128<2><<<dim3(4, 64, 1), 256, GEMM_DYN>>>(                             // 10: Qp
        (__nv_bfloat16*)gQb, (__nv_bfloat16*)gwqt, bq,
        (__nv_bfloat16*)gQp, nullptr, 512, SQ, 0, 0, 0, nullptr);
    score_mma<<<dim3(16, 16, BATCH*NHEAD), 256, SC_DYN>>>((float*)ghs);        // 11
    combine_kernel<<<BATCH*SQ, 256>>>(kwpos, adj);                             // 12
    transpose_val<<<dim3(16, 64, BATCH), 256>>>(value);                        // 13
    gemm128<4><<<dim3(4, 16, BATCH), 256, GEMM_DYN>>>(                         // 14: out
        (__nv_bfloat16*)gdelta, (__nv_bfloat16*)gvalT, nullptr,
        nullptr, out, 2048, SQ, (long)SQ*SK, (long)512*2048, (long)SQ*512,
        (const float*)gsv);
}

// round 6
// speedup vs baseline: 1.0912x; 1.0471x over previous
#include <cuda_runtime.h>
#include <cuda_bf16.h>
#include <cuda_fp16.h>
#include <math.h>
#include <stdint.h>

#define BATCH 4
#define SQ    2048
#define SK    2048
#define NHEAD 8
#define MROWS (BATCH*SK)   // 8192

// ---------------------------------------------------------------------------
// Device scratch
// ---------------------------------------------------------------------------
__device__ __align__(16) __nv_bfloat16 g_KP  [(long)MROWS*576];
__device__ __align__(16) __nv_bfloat16 g_Qb  [(long)MROWS*512];
__device__ __align__(16) __nv_bfloat16 g_w1t [512*576];
__device__ __align__(16) __nv_bfloat16 g_w2t [512*512];
__device__ __align__(16) __nv_bfloat16 g_wqt [512*512];
__device__ __align__(16) __nv_bfloat16 g_wkt [512*512];
__device__ __align__(16) __nv_bfloat16 g_H   [(long)MROWS*512];
__device__ __align__(16) __nv_bfloat16 g_E   [(long)MROWS*512];
__device__ __align__(16) __nv_bfloat16 g_Qp  [(long)MROWS*512];   // (B,H,Sq,64)
__device__ __align__(16) __nv_bfloat16 g_Kp  [(long)MROWS*512];   // (B,H,Sk,64)
__device__ __align__(16) unsigned char g_expS8[(long)BATCH*NHEAD*SQ*SK]; // 134MB, e4m3 of exp-1
__device__ __align__(16) __nv_bfloat16 g_delta[(long)BATCH*SQ*SK];
__device__ __align__(16) __nv_bfloat16 g_valT[(long)BATCH*512*2048];
__device__ float g_sv[BATCH*512];
__device__ float g_headSum[(long)BATCH*NHEAD*SQ];

// ---------------------------------------------------------------------------
// Helpers
// ---------------------------------------------------------------------------
__device__ __forceinline__ uint32_t smem_u32(const void* p) {
    uint32_t a;
    asm("{ .reg .u64 t; cvta.to.shared.u64 t, %1; cvt.u32.u64 %0, t; }"
        : "=r"(a) : "l"(p));
    return a;
}
__device__ __forceinline__ void ldm_x4(uint32_t& r0, uint32_t& r1,
                                       uint32_t& r2, uint32_t& r3, uint32_t a) {
    asm volatile("ldmatrix.sync.aligned.m8n8.x4.shared.b16 {%0,%1,%2,%3}, [%4];"
                 : "=r"(r0), "=r"(r1), "=r"(r2), "=r"(r3) : "r"(a));
}
__device__ __forceinline__ void mma16816(float* c, uint32_t a0, uint32_t a1,
                                         uint32_t a2, uint32_t a3,
                                         uint32_t b0, uint32_t b1) {
    asm volatile("mma.sync.aligned.m16n8k16.row.col.f32.bf16.bf16.f32 "
                 "{%0,%1,%2,%3},{%4,%5,%6,%7},{%8,%9},{%0,%1,%2,%3};"
                 : "+f"(c[0]), "+f"(c[1]), "+f"(c[2]), "+f"(c[3])
                 : "r"(a0), "r"(a1), "r"(a2), "r"(a3), "r"(b0), "r"(b1));
}
#define CP_ASYNC16(dst, src) \
    asm volatile("cp.async.cg.shared.global [%0], [%1], 16;" :: "r"(dst), "l"(src))
#define CP_COMMIT() asm volatile("cp.async.commit_group;")
#define CP_WAIT(n)  asm volatile("cp.async.wait_group %0;" :: "n"(n))

__device__ __forceinline__ unsigned short f2_to_fp8x2(float hi, float lo) {
    unsigned short u;
    asm("cvt.rn.satfinite.e4m3x2.f32 %0, %1, %2;" : "=h"(u) : "f"(hi), "f"(lo));
    return u;
}
__device__ __forceinline__ float2 fp8x2_to_f2(unsigned short u) {
    uint32_t h2;
    asm("cvt.rn.f16x2.e4m3x2 %0, %1;" : "=r"(h2) : "h"(u));
    return __half22float2(*reinterpret_cast<__half2*>(&h2));
}

// ---------------------------------------------------------------------------
// GEMM 128x128, BK=64: C = epi(A[M,K] @ Bt[N,K]^T)
//   256 threads, 8 warps (2m x 4n), warp tile 64x32, 3-stage cp.async,
//   one __syncthreads per 64-wide K-iter, 2 CTAs/SM.
// EPI: 0 relu+bias->bf16   1 tanh+bias->bf16   2 bias->bf16 head-split
//      4 +sv/2048 -> fp32
// ---------------------------------------------------------------------------
#define STAGE_BYTES 36864            // A: 128*144, B: 128*144
#define GEMM_DYN (3*STAGE_BYTES)     // 110592

template<int EPI>
__global__ void __launch_bounds__(256, 2)
gemm128(const __nv_bfloat16* __restrict__ A,
        const __nv_bfloat16* __restrict__ Bt,
        const float* __restrict__ bias,
        __nv_bfloat16* __restrict__ Cb,
        float* __restrict__ Cf,
        int K, int S, long a_bstr, long b_bstr, long c_bstr,
        const float* __restrict__ sv)
{
    extern __shared__ __align__(16) char smem[];
    __shared__ float sbias[128];

    const int tid = threadIdx.x, lane = tid & 31, wid = tid >> 5;
    const int wm = wid >> 2, wn = wid & 3;          // 2 x 4 warps
    const int g = lane >> 2, tg = lane & 3;
    const int z = blockIdx.z;
    const int m0 = blockIdx.y * 128, n0 = blockIdx.x * 128;

    A  += (long)z * a_bstr;
    Bt += (long)z * b_bstr;

    if (tid < 128) {
        if (EPI <= 2) sbias[tid] = bias[n0 + tid];
        if (EPI == 4) sbias[tid] = sv[z*512 + n0 + tid] * (1.0f/2048.0f);
    }

    float acc[4][4][4];
    #pragma unroll
    for (int i = 0; i < 4; i++)
        #pragma unroll
        for (int j = 0; j < 4; j++)
            #pragma unroll
            for (int r = 0; r < 4; r++) acc[i][j][r] = 0.f;

    const int nk = K >> 6;

    auto prefetch = [&](int t) {
        if (t >= nk) return;
        int kt = t * 64;
        char* base = smem + (t % 3) * STAGE_BYTES;
        #pragma unroll
        for (int i = 0; i < 4; i++) {                 // A: 128 rows x 8 chunks
            int ch = tid + i*256;
            int r = ch >> 3, off = (ch & 7) * 8;
            CP_ASYNC16(smem_u32(base + r*144 + off*2),
                       A + (long)(m0 + r)*K + kt + off);
        }
        #pragma unroll
        for (int i = 0; i < 4; i++) {                 // B: 128 rows x 8 chunks
            int ch = tid + i*256;
            int r = ch >> 3, off = (ch & 7) * 8;
            CP_ASYNC16(smem_u32(base + 18432 + r*144 + off*2),
                       Bt + (long)(n0 + r)*K + kt + off);
        }
    };

    prefetch(0); CP_COMMIT();
    prefetch(1); CP_COMMIT();

    const int arow = lane & 15;
    const int acol = (lane & 16) ? 8 : 0;
    const int brow = ((lane >> 4) & 1) * 8 + (lane & 7);
    const int bcol = ((lane >> 3) & 1) * 8;

    for (int t = 0; t < nk; ++t) {
        CP_WAIT(1);
        __syncthreads();
        prefetch(t + 2); CP_COMMIT();   // buffer freed at t-1, barrier-ordered
        char* base = smem + (t % 3) * STAGE_BYTES;
        #pragma unroll
        for (int ks = 0; ks < 4; ++ks) {
            uint32_t a[4][4], b[4][2];
            #pragma unroll
            for (int mi = 0; mi < 4; ++mi) {
                uint32_t ad = smem_u32(base + (wm*64 + mi*16 + arow)*144
                                            + (ks*16 + acol)*2);
                ldm_x4(a[mi][0], a[mi][1], a[mi][2], a[mi][3], ad);
            }
            #pragma unroll
            for (int p = 0; p < 2; ++p) {
                uint32_t bd = smem_u32(base + 18432 + (wn*32 + p*16 + brow)*144
                                             + (ks*16 + bcol)*2);
                ldm_x4(b[2*p][0], b[2*p][1], b[2*p+1][0], b[2*p+1][1], bd);
            }
            #pragma unroll
            for (int mi = 0; mi < 4; ++mi)
                #pragma unroll
                for (int nj = 0; nj < 4; ++nj)
                    mma16816(acc[mi][nj], a[mi][0], a[mi][1], a[mi][2], a[mi][3],
                             b[nj][0], b[nj][1]);
        }
    }

    // ---------------- epilogue (register -> global) ----------------
    #pragma unroll
    for (int mi = 0; mi < 4; ++mi) {
        #pragma unroll
        for (int half = 0; half < 2; ++half) {
            int m = m0 + wm*64 + mi*16 + g + half*8;
            #pragma unroll
            for (int nj = 0; nj < 4; ++nj) {
                int nl = wn*32 + nj*8 + tg*2;
                int n = n0 + nl;
                float v0 = acc[mi][nj][half*2 + 0];
                float v1 = acc[mi][nj][half*2 + 1];
                if (EPI <= 2) {
                    v0 += sbias[nl]; v1 += sbias[nl+1];
                    if (EPI == 0) { v0 = fmaxf(v0, 0.f); v1 = fmaxf(v1, 0.f); }
                    if (EPI == 1) { v0 = tanhf(v0);      v1 = tanhf(v1); }
                    __nv_bfloat162 pk;
                    pk.x = __float2bfloat16(v0); pk.y = __float2bfloat16(v1);
                    if (EPI == 2) {
                        int b = m / S, srow = m - b*S;
                        int h = n >> 6, dd = n & 63;
                        long idx = (((long)(b*NHEAD + h)*S + srow) << 6) + dd;
                        *(__nv_bfloat162*)&Cb[idx] = pk;
                    } else {
                        *(__nv_bfloat162*)&Cb[(long)m*512 + n] = pk;
                    }
                } else { // EPI == 4
                    float o0 = v0 + sbias[nl];
                    float o1 = v1 + sbias[nl+1];
                    *(float2*)&Cf[(long)z*c_bstr + (long)m*512 + n] = make_float2(o0, o1);
                }
            }
        }
    }
}

// ---------------------------------------------------------------------------
// Score GEMM: per (b,h) 128x128 tile, exp(Qp·Kp^T/8); store fp8(e-1); rowsums.
// ---------------------------------------------------------------------------
#define SC_DYN (2*128*144)

__global__ void __launch_bounds__(256)
score_mma(float* __restrict__ rowsum)
{
    extern __shared__ __align__(16) char smem[];
    __shared__ float srs[128];

    const int tid = threadIdx.x, lane = tid & 31, wid = tid >> 5;
    const int wm = wid >> 2, wn = wid & 3;
    const int g = lane >> 2, tg = lane & 3;
    const int z = blockIdx.z;
    const int m0 = blockIdx.y * 128, n0 = blockIdx.x * 128;

    const __nv_bfloat16* A  = g_Qp + (long)z * 2048 * 64;
    const __nv_bfloat16* Bt = g_Kp + (long)z * 2048 * 64;

    if (tid < 128) srs[tid] = 0.f;

    char* sA = smem;
    char* sB = smem + 128*144;
    #pragma unroll
    for (int i = 0; i < 4; i++) {
        int ch = tid + i*256;
        int r = ch >> 3, off = (ch & 7) * 8;
        CP_ASYNC16(smem_u32(sA + r*144 + off*2), A  + (long)(m0 + r)*64 + off);
        CP_ASYNC16(smem_u32(sB + r*144 + off*2), Bt + (long)(n0 + r)*64 + off);
    }
    CP_COMMIT();
    CP_WAIT(0);
    __syncthreads();

    const int arow = lane & 15;
    const int acol = (lane & 16) ? 8 : 0;
    const int brow = ((lane >> 4) & 1) * 8 + (lane & 7);
    const int bcol = ((lane >> 3) & 1) * 8;

    float acc[4][4][4];
    #pragma unroll
    for (int i = 0; i < 4; i++)
        #pragma unroll
        for (int j = 0; j < 4; j++)
            #pragma unroll
            for (int r = 0; r < 4; r++) acc[i][j][r] = 0.f;

    #pragma unroll
    for (int ks = 0; ks < 4; ++ks) {
        uint32_t a[4][4], b[4][2];
        #pragma unroll
        for (int mi = 0; mi < 4; ++mi) {
            uint32_t ad = smem_u32(sA + (wm*64 + mi*16 + arow)*144
                                      + (ks*16 + acol)*2);
            ldm_x4(a[mi][0], a[mi][1], a[mi][2], a[mi][3], ad);
        }
        #pragma unroll
        for (int p = 0; p < 2; ++p) {
            uint32_t bd = smem_u32(sB + (wn*32 + p*16 + brow)*144
                                      + (ks*16 + bcol)*2);
            ldm_x4(b[2*p][0], b[2*p][1], b[2*p+1][0], b[2*p+1][1], bd);
        }
        #pragma unroll
        for (int mi = 0; mi < 4; ++mi)
            #pragma unroll
            for (int nj = 0; nj < 4; ++nj)
                mma16816(acc[mi][nj], a[mi][0], a[mi][1], a[mi][2], a[mi][3],
                         b[nj][0], b[nj][1]);
    }

    #pragma unroll
    for (int mi = 0; mi < 4; ++mi) {
        #pragma unroll
        for (int half = 0; half < 2; ++half) {
            int m = m0 + wm*64 + mi*16 + g + half*8;
            float rsum = 0.f;
            #pragma unroll
            for (int nj = 0; nj < 4; ++nj) {
                int n = n0 + wn*32 + nj*8 + tg*2;
                float v0 = __expf(acc[mi][nj][half*2 + 0] * 0.125f);
                float v1 = __expf(acc[mi][nj][half*2 + 1] * 0.125f);
                rsum += v0 + v1;
                unsigned short u = f2_to_fp8x2(v1 - 1.f, v0 - 1.f);  // lo byte = v0
                *(unsigned short*)&g_expS8[(long)z*SQ*SK + (long)m*2048 + n] = u;
            }
            rsum += __shfl_xor_sync(0xffffffffu, rsum, 1);
            rsum += __shfl_xor_sync(0xffffffffu, rsum, 2);
            if (tg == 0) atomicAdd(&srs[m - m0], rsum);
        }
    }
    __syncthreads();
    if (tid < 128) atomicAdd(&rowsum[(long)z*SQ + m0 + tid], srs[tid]);
}

// ---------------------------------------------------------------------------
// Prep + combine kernels
// ---------------------------------------------------------------------------
__global__ void zero_kernel() {
    int i = blockIdx.x * blockDim.x + threadIdx.x;
    if (i < BATCH*NHEAD*SQ) g_headSum[i] = 0.f;
    if (i < BATCH*512)      g_sv[i] = 0.f;
}

__global__ void convert_concat(const float* __restrict__ key,
                               const int* __restrict__ kwpos,
                               const float* __restrict__ pe)
{
    int i = blockIdx.x * blockDim.x + threadIdx.x;
    if (i >= MROWS * 144) return;
    int row = i / 144, c4 = (i % 144) * 4;
    float4 v;
    if (c4 < 512) v = *(const float4*)&key[(long)row*512 + c4];
    else { int p = kwpos[row]; v = *(const float4*)&pe[(long)p*64 + (c4-512)]; }
    __nv_bfloat162 p0, p1;
    p0.x = __float2bfloat16(v.x); p0.y = __float2bfloat16(v.y);
    p1.x = __float2bfloat16(v.z); p1.y = __float2bfloat16(v.w);
    __nv_bfloat16* d = &g_KP[(long)row*576 + c4];
    *(__nv_bfloat162*)&d[0] = p0;
    *(__nv_bfloat162*)&d[2] = p1;
}

__global__ void conv_bf16(const float* __restrict__ src,
                          __nv_bfloat16* __restrict__ dst, int n4)
{
    int i = blockIdx.x * blockDim.x + threadIdx.x;
    if (i >= n4) return;
    float4 v = *(const float4*)&src[(long)i*4];
    __nv_bfloat162 p0, p1;
    p0.x = __float2bfloat16(v.x); p0.y = __float2bfloat16(v.y);
    p1.x = __float2bfloat16(v.z); p1.y = __float2bfloat16(v.w);
    *(__nv_bfloat162*)&dst[(long)i*4]   = p0;
    *(__nv_bfloat162*)&dst[(long)i*4+2] = p1;
}

__global__ void transpose_conv(const float* __restrict__ src,
                               __nv_bfloat16* __restrict__ dst,
                               int R, int C)
{
    __shared__ float t[32][33];
    int r0 = blockIdx.y * 32, c0 = blockIdx.x * 32;
    int tx = threadIdx.x & 31, ty = threadIdx.x >> 5;
    #pragma unroll
    for (int i = 0; i < 4; i++)
        t[ty + i*8][tx] = src[(long)(r0 + ty + i*8)*C + c0 + tx];
    __syncthreads();
    #pragma unroll
    for (int i = 0; i < 4; i++)
        dst[(long)(c0 + ty + i*8)*R + r0 + tx] = __float2bfloat16(t[tx][ty + i*8]);
}

__global__ void transpose_val(const float* __restrict__ value)
{
    __shared__ float t[32][33];
    int b = blockIdx.z;
    const float* src = value + (long)b*SK*512;
    __nv_bfloat16* dst = g_valT + (long)b*512*2048;
    int r0 = blockIdx.y * 32, c0 = blockIdx.x * 32;
    int tx = threadIdx.x & 31, ty = threadIdx.x >> 5;
    #pragma unroll
    for (int i = 0; i < 4; i++)
        t[ty + i*8][tx] = src[(long)(r0 + ty + i*8)*512 + c0 + tx];
    __syncthreads();
    #pragma unroll
    for (int i = 0; i < 4; i++)
        dst[(long)(c0 + ty + i*8)*2048 + r0 + tx] = __float2bfloat16(t[tx][ty + i*8]);
    if (threadIdx.x < 32) {
        float s = 0.f;
        #pragma unroll
        for (int rl = 0; rl < 32; rl++) s += t[rl][threadIdx.x];
        atomicAdd(&g_sv[b*512 + c0 + threadIdx.x], s);
    }
}

// Combine: attn = c0 + (1/8)Σ_h s'_hk·invZ_h, adjusted = softmax(attn*dw)
// Thread owns 8 consecutive k (blocked).
__global__ void combine_kernel(const int* __restrict__ kwpos,
                               float* __restrict__ adj)
{
    int bq = blockIdx.x;
    int b  = bq >> 11;
    int q  = bq & 2047;
    int tid = threadIdx.x;
    int k0 = tid * 8;

    __shared__ float invHS[NHEAD];
    if (tid < NHEAD)
        invHS[tid] = 1.0f / g_headSum[(long)(b*NHEAD + tid)*SQ + q];
    __syncthreads();

    float c0 = 0.f;
    #pragma unroll
    for (int h = 0; h < NHEAD; h++) c0 += invHS[h];
    c0 *= 0.125f;

    float acc[8] = {0.f,0.f,0.f,0.f,0.f,0.f,0.f,0.f};
    #pragma unroll
    for (int h = 0; h < NHEAD; h++) {
        const unsigned char* rowp =
            g_expS8 + ((long)(b*NHEAD + h)*SQ + q)*SK + k0;
        uint2 raw = *(const uint2*)rowp;
        float w = invHS[h];
        float2 f0 = fp8x2_to_f2((unsigned short)(raw.x & 0xFFFF));
        float2 f1 = fp8x2_to_f2((unsigned short)(raw.x >> 16));
        float2 f2 = fp8x2_to_f2((unsigned short)(raw.y & 0xFFFF));
        float2 f3 = fp8x2_to_f2((unsigned short)(raw.y >> 16));
        acc[0] = fmaf(f0.x, w, acc[0]); acc[1] = fmaf(f0.y, w, acc[1]);
        acc[2] = fmaf(f1.x, w, acc[2]); acc[3] = fmaf(f1.y, w, acc[3]);
        acc[4] = fmaf(f2.x, w, acc[4]); acc[5] = fmaf(f2.y, w, acc[5]);
        acc[6] = fmaf(f3.x, w, acc[6]); acc[7] = fmaf(f3.y, w, acc[7]);
    }

    int4 kpa = *(const int4*)&kwpos[b*SK + k0];
    int4 kpb = *(const int4*)&kwpos[b*SK + k0 + 4];
    int kparr[8] = {kpa.x, kpa.y, kpa.z, kpa.w, kpb.x, kpb.y, kpb.z, kpb.w};

    float e[8];
    float sum = 0.f;
    #pragma unroll
    for (int i = 0; i < 8; i++) {
        float attn = fmaf(0.125f, acc[i], c0);
        float dw = 1.0f / (1.0f + fabsf((float)(q - kparr[i])));
        e[i] = __expf(attn * dw);
        sum += e[i];
    }

    #pragma unroll
    for (int s = 16; s > 0; s >>= 1) sum += __shfl_xor_sync(0xffffffffu, sum, s);
    __shared__ float wred[8];
    if ((tid & 31) == 0) wred[tid >> 5] = sum;
    __syncthreads();
    float tot = wred[0];
    #pragma unroll
    for (int w = 1; w < 8; w++) tot += wred[w];
    float inv = 1.0f / tot;

    long base = (long)bq * SK;
    float av[8];
    #pragma unroll
    for (int i = 0; i < 8; i++) av[i] = e[i] * inv;
    *(float4*)&adj[base + k0]     = make_float4(av[0], av[1], av[2], av[3]);
    *(float4*)&adj[base + k0 + 4] = make_float4(av[4], av[5], av[6], av[7]);

    __nv_bfloat162 d01, d23, d45, d67;
    const float C = 1.f/2048.f;
    d01.x = __float2bfloat16(av[0]-C); d01.y = __float2bfloat16(av[1]-C);
    d23.x = __float2bfloat16(av[2]-C); d23.y = __float2bfloat16(av[3]-C);
    d45.x = __float2bfloat16(av[4]-C); d45.y = __float2bfloat16(av[5]-C);
    d67.x = __float2bfloat16(av[6]-C); d67.y = __float2bfloat16(av[7]-C);
    uint4 dp;
    dp.x = *(uint32_t*)&d01; dp.y = *(uint32_t*)&d23;
    dp.z = *(uint32_t*)&d45; dp.w = *(uint32_t*)&d67;
    *(uint4*)&g_delta[base + k0] = dp;
}

// ---------------------------------------------------------------------------
extern "C" void kernel_launch(void* const* d_in, const int* in_sizes, int n_in,
                              void* d_out, int out_size)
{
    const float* query   = (const float*)d_in[0];
    const float* key     = (const float*)d_in[1];
    const float* value   = (const float*)d_in[2];
    const int*   kwpos   = (const int*)  d_in[3];
    const float* pos_emb = (const float*)d_in[4];
    const float* w1      = (const float*)d_in[5];
    const float* b1      = (const float*)d_in[6];
    const float* w2      = (const float*)d_in[7];
    const float* b2      = (const float*)d_in[8];
    const float* wq      = (const float*)d_in[9];
    const float* bq      = (const float*)d_in[10];
    const float* wk      = (const float*)d_in[11];
    const float* bk      = (const float*)d_in[12];

    float* out = (float*)d_out;
    float* adj = out + (long)BATCH*SQ*512;

    void *gKP, *gQb, *gw1t, *gw2t, *gwqt, *gwkt, *gH, *gE, *gQp, *gKp,
         *gdelta, *gvalT, *gsv, *ghs;
    cudaGetSymbolAddress(&gKP,   g_KP);
    cudaGetSymbolAddress(&gQb,   g_Qb);
    cudaGetSymbolAddress(&gw1t,  g_w1t);
    cudaGetSymbolAddress(&gw2t,  g_w2t);
    cudaGetSymbolAddress(&gwqt,  g_wqt);
    cudaGetSymbolAddress(&gwkt,  g_wkt);
    cudaGetSymbolAddress(&gH,    g_H);
    cudaGetSymbolAddress(&gE,    g_E);
    cudaGetSymbolAddress(&gQp,   g_Qp);
    cudaGetSymbolAddress(&gKp,   g_Kp);
    cudaGetSymbolAddress(&gdelta,g_delta);
    cudaGetSymbolAddress(&gvalT, g_valT);
    cudaGetSymbolAddress(&gsv,   g_sv);
    cudaGetSymbolAddress(&ghs,   g_headSum);

    cudaFuncSetAttribute(gemm128<0>, cudaFuncAttributeMaxDynamicSharedMemorySize, GEMM_DYN);
    cudaFuncSetAttribute(gemm128<1>, cudaFuncAttributeMaxDynamicSharedMemorySize, GEMM_DYN);
    cudaFuncSetAttribute(gemm128<2>, cudaFuncAttributeMaxDynamicSharedMemorySize, GEMM_DYN);
    cudaFuncSetAttribute(gemm128<4>, cudaFuncAttributeMaxDynamicSharedMemorySize, GEMM_DYN);
    cudaFuncSetAttribute(score_mma,  cudaFuncAttributeMaxDynamicSharedMemorySize, SC_DYN);

    // launch order: index 5 = gemm128<1> (E) for ncu -s 5
    zero_kernel<<<(BATCH*NHEAD*SQ + 255)/256, 256>>>();                        // 0
    convert_concat<<<(MROWS*144 + 255)/256, 256>>>(key, kwpos, pos_emb);       // 1
    transpose_conv<<<dim3(16, 18, 1), 256>>>(w1, (__nv_bfloat16*)gw1t, 576, 512); // 2
    gemm128<0><<<dim3(4, 64, 1), 256, GEMM_DYN>>>(                             // 3: H
        (__nv_bfloat16*)gKP, (__nv_bfloat16*)gw1t, b1,
        (__nv_bfloat16*)gH, nullptr, 576, SK, 0, 0, 0, nullptr);
    transpose_conv<<<dim3(16, 16, 1), 256>>>(w2, (__nv_bfloat16*)gw2t, 512, 512); // 4
    gemm128<1><<<dim3(4, 64, 1), 256, GEMM_DYN>>>(                             // 5: E
        (__nv_bfloat16*)gH, (__nv_bfloat16*)gw2t, b2,
        (__nv_bfloat16*)gE, nullptr, 512, SK, 0, 0, 0, nullptr);
    transpose_conv<<<dim3(16, 16, 1), 256>>>(wk, (__nv_bfloat16*)gwkt, 512, 512); // 6
    gemm128<2><<<dim3(4, 64, 1), 256, GEMM_DYN>>>(                             // 7: Kp
        (__nv_bfloat16*)gE, (__nv_bfloat16*)gwkt, bk,
        (__nv_bfloat16*)gKp, nullptr, 512, SK, 0, 0, 0, nullptr);
    conv_bf16<<<(MROWS*512/4 + 255)/256, 256>>>(query, (__nv_bfloat16*)gQb, MROWS*512/4); // 8
    transpose_conv<<<dim3(16, 16, 1), 256>>>(wq, (__nv_bfloat16*)gwqt, 512, 512);         // 9
    gemm128<2><<<dim3(4, 64, 1), 256, GEMM_DYN>>>(                             // 10: Qp
        (__nv_bfloat16*)gQb, (__nv_bfloat16*)gwqt, bq,
        (__nv_bfloat16*)gQp, nullptr, 512, SQ, 0, 0, 0, nullptr);
    score_mma<<<dim3(16, 16, BATCH*NHEAD), 256, SC_DYN>>>((float*)ghs);        // 11
    combine_kernel<<<BATCH*SQ, 256>>>(kwpos, adj);                             // 12
    transpose_val<<<dim3(16, 64, BATCH), 256>>>(value);                        // 13
    gemm128<4><<<dim3(4, 16, BATCH), 256, GEMM_DYN>>>(                         // 14: out
        (__nv_bfloat16*)gdelta, (__nv_bfloat16*)gvalT, nullptr,
        nullptr, out, 2048, SQ, (long)SQ*SK, (long)512*2048, (long)SQ*512,
        (const float*)gsv);
}